// round 5
// baseline (speedup 1.0000x reference)
#include <cuda_runtime.h>
#include <cuda_bf16.h>
#include <cstdint>

// Problem constants
#define N_MET   100000
#define N_RXN   50000
#define E_SUB   2000000
#define E_ALL   4000000
#define MSG_DIM 16
#define HIDDEN  32

// Persistent scratch: per-reaction accumulated messages [N_RXN][16]
__device__ float g_hrxn[N_RXN * MSG_DIM];

// ---------------------------------------------------------------------------
// helpers
// ---------------------------------------------------------------------------
__device__ __forceinline__ unsigned long long pack2(float a, float b) {
    unsigned long long r;
    asm("mov.b64 %0, {%1,%2};" : "=l"(r) : "f"(a), "f"(b));
    return r;
}
__device__ __forceinline__ unsigned long long fma2(unsigned long long a,
                                                   unsigned long long b,
                                                   unsigned long long c) {
    unsigned long long d;
    asm("fma.rn.f32x2 %0, %1, %2, %3;" : "=l"(d) : "l"(a), "l"(b), "l"(c));
    return d;
}
__device__ __forceinline__ float2 unpack2(unsigned long long a) {
    float2 f;
    asm("mov.b64 {%0,%1}, %2;" : "=f"(f.x), "=f"(f.y) : "l"(a));
    return f;
}
__device__ __forceinline__ float fast_ex2(float x) {
    float y; asm("ex2.approx.ftz.f32 %0, %1;" : "=f"(y) : "f"(x)); return y;
}
__device__ __forceinline__ float fast_rcp(float x) {
    float y; asm("rcp.approx.ftz.f32 %0, %1;" : "=f"(y) : "f"(x)); return y;
}
// single-MUFU tanh (MUFU.TANH) — edge kernel (measured: no precision impact)
__device__ __forceinline__ float tanh_fast(float x) {
    float y; asm("tanh.approx.f32 %0, %1;" : "=f"(y) : "f"(x)); return y;
}
// accurate tanh via ex2+rcp (input pre-scaled by 2*log2(e)) — rate kernel
__device__ __forceinline__ float tanh_from_scaled(float u_scaled) {
    float e = fast_ex2(u_scaled);
    float r = fast_rcp(e + 1.0f);
    return fmaf(-2.0f, r, 1.0f);
}

__device__ __forceinline__ void red_add_v4(float* p, float a, float b, float c, float d) {
    asm volatile("red.global.add.v4.f32 [%0], {%1,%2,%3,%4};"
                 :: "l"(p), "f"(a), "f"(b), "f"(c), "f"(d) : "memory");
}
__device__ __forceinline__ void red_add_f32(float* p, float a) {
    asm volatile("red.global.add.f32 [%0], %1;" :: "l"(p), "f"(a) : "memory");
}

// ---------------------------------------------------------------------------
// Kernel 1: per-edge message MLP + scatter-add into g_hrxn
//   msg = tanh([x,s] @ W1m + b1m) @ W2m + b2m      (2->32->16)
// ---------------------------------------------------------------------------
#define K1_TPB 256
#define K1_EPT 4
#define K1_EPB (K1_TPB * K1_EPT)

__global__ __launch_bounds__(K1_TPB)
void edge_msg_kernel(const float* __restrict__ x_met,
                     const float* __restrict__ sto_sub,
                     const float* __restrict__ W1m,
                     const float* __restrict__ b1m,
                     const float* __restrict__ W2m,
                     const float* __restrict__ b2m,
                     const int*   __restrict__ met_sub,
                     const int*   __restrict__ rxn_sub) {
    __shared__ float4 sW1[HIDDEN];                       // {a, b, bias, 0}
    __shared__ unsigned long long sW2p[HIDDEN * 8];      // row j: 8 packed f32 pairs
    __shared__ float  sB2[MSG_DIM];

    const int t = threadIdx.x;
    if (t < HIDDEN) {
        sW1[t] = make_float4(W1m[t], W1m[HIDDEN + t], b1m[t], 0.f);
    }
    {   // pack W2m[j][2q], W2m[j][2q+1] -> u64
        int j = t >> 3, q = t & 7;
        if (t < HIDDEN * 8) {
            float2 w = reinterpret_cast<const float2*>(W2m)[j * (MSG_DIM / 2) + q];
            sW2p[j * 8 + q] = pack2(w.x, w.y);
        }
    }
    if (t < MSG_DIM) sB2[t] = b2m[t];
    __syncthreads();

    const int base = blockIdx.x * K1_EPB + t;
    float x[K1_EPT], s[K1_EPT];
    int   rx[K1_EPT];
    #pragma unroll
    for (int k = 0; k < K1_EPT; k++) {
        int e = base + k * K1_TPB;
        if (e < E_SUB) {
            int m = __ldcs(met_sub + e);          // streaming: evict-first
            x[k]  = __ldg(x_met + m);             // keep x_met L1-resident
            s[k]  = __ldcs(sto_sub + e);
            rx[k] = __ldcs(rxn_sub + e);
        } else {
            x[k] = 0.f; s[k] = 0.f; rx[k] = -1;
        }
    }

    unsigned long long acc[K1_EPT][MSG_DIM / 2];
    {
        unsigned long long binit[MSG_DIM / 2];
        #pragma unroll
        for (int q = 0; q < MSG_DIM / 2; q++) binit[q] = pack2(sB2[2 * q], sB2[2 * q + 1]);
        #pragma unroll
        for (int k = 0; k < K1_EPT; k++)
            #pragma unroll
            for (int q = 0; q < MSG_DIM / 2; q++) acc[k][q] = binit[q];
    }

    #pragma unroll 2
    for (int j = 0; j < HIDDEN; j++) {
        float4 w1 = sW1[j];
        const unsigned long long* w2p = &sW2p[j * 8];
        float h[K1_EPT];
        #pragma unroll
        for (int k = 0; k < K1_EPT; k++) {
            float u = fmaf(x[k], w1.x, fmaf(s[k], w1.y, w1.z));
            h[k] = tanh_fast(u);
        }
        #pragma unroll
        for (int k = 0; k < K1_EPT; k++) {
            unsigned long long hh = pack2(h[k], h[k]);
            #pragma unroll
            for (int q = 0; q < MSG_DIM / 2; q++)
                acc[k][q] = fma2(hh, w2p[q], acc[k][q]);
        }
    }

    #pragma unroll
    for (int k = 0; k < K1_EPT; k++) {
        if (rx[k] >= 0) {
            float* p = g_hrxn + (size_t)rx[k] * MSG_DIM;
            #pragma unroll
            for (int q = 0; q < 4; q++) {
                float2 a = unpack2(acc[k][2 * q]);
                float2 b = unpack2(acc[k][2 * q + 1]);
                red_add_v4(p + 4 * q, a.x, a.y, b.x, b.y);
            }
        }
    }
}

// ---------------------------------------------------------------------------
// Kernel 2: per-reaction rate MLP (exact tanh for precision headroom)
// ---------------------------------------------------------------------------
__global__ __launch_bounds__(256)
void rate_kernel(const float* __restrict__ W1r,
                 const float* __restrict__ b1r,
                 const float* __restrict__ W2r,
                 const float* __restrict__ b2r,
                 float* __restrict__ v_out) {
    __shared__ float sW1r[MSG_DIM * HIDDEN];
    __shared__ float sb1r[HIDDEN];
    __shared__ float sW2r[HIDDEN];
    __shared__ float sb2r;

    int t = threadIdx.x;
    for (int i = t; i < MSG_DIM * HIDDEN; i += blockDim.x) sW1r[i] = W1r[i];
    if (t < HIDDEN) { sb1r[t] = b1r[t]; sW2r[t] = W2r[t]; }
    if (t == 0) sb2r = b2r[0];
    __syncthreads();

    int r = blockIdx.x * blockDim.x + t;
    if (r >= N_RXN) return;

    float h[MSG_DIM];
    const float4* hp = reinterpret_cast<const float4*>(g_hrxn + (size_t)r * MSG_DIM);
    #pragma unroll
    for (int q = 0; q < 4; q++) {
        float4 hv = hp[q];
        h[4 * q] = hv.x; h[4 * q + 1] = hv.y; h[4 * q + 2] = hv.z; h[4 * q + 3] = hv.w;
    }

    const float C = 2.8853900817779268f;  // 2*log2(e)
    float y = sb2r;
    #pragma unroll 8
    for (int j = 0; j < HIDDEN; j++) {
        float a = sb1r[j];
        #pragma unroll
        for (int k = 0; k < MSG_DIM; k++) a = fmaf(h[k], sW1r[k * HIDDEN + j], a);
        float z = tanh_from_scaled(a * C);
        y = fmaf(z, sW2r[j], y);
    }
    float sp = fmaxf(y, 0.f) + log1pf(expf(-fabsf(y)));
    v_out[r] = sp;
}

// ---------------------------------------------------------------------------
// Kernel 3: dxdt scatter — 8 edges/thread, all stream loads front-batched
// to maximize memory-level parallelism (latency-bound per R4 ncu: issue=3.4%)
// ---------------------------------------------------------------------------
#define K3_EPT 8   // edges per thread

__global__ __launch_bounds__(256)
void dxdt_kernel(const float* __restrict__ sto_all,
                 const int*   __restrict__ rxn_all,
                 const int*   __restrict__ met_all,
                 const float* __restrict__ v,
                 float* __restrict__ dxdt) {
    int i8 = blockIdx.x * blockDim.x + threadIdx.x;   // one thread = 8 edges
    const int n8 = E_ALL / K3_EPT;                    // 500000
    if (i8 >= n8) return;

    // front-batched streaming loads: 6 independent LDG.128
    float4 st0 = __ldcs(reinterpret_cast<const float4*>(sto_all) + 2 * i8);
    float4 st1 = __ldcs(reinterpret_cast<const float4*>(sto_all) + 2 * i8 + 1);
    int4   rv0 = __ldcs(reinterpret_cast<const int4*>(rxn_all) + 2 * i8);
    int4   rv1 = __ldcs(reinterpret_cast<const int4*>(rxn_all) + 2 * i8 + 1);
    int4   mv0 = __ldcs(reinterpret_cast<const int4*>(met_all) + 2 * i8);
    int4   mv1 = __ldcs(reinterpret_cast<const int4*>(met_all) + 2 * i8 + 1);

    // 8 independent gathers of v (L1/L2)
    float v0 = __ldg(v + rv0.x), v1 = __ldg(v + rv0.y);
    float v2 = __ldg(v + rv0.z), v3 = __ldg(v + rv0.w);
    float v4 = __ldg(v + rv1.x), v5 = __ldg(v + rv1.y);
    float v6 = __ldg(v + rv1.z), v7 = __ldg(v + rv1.w);

    red_add_f32(dxdt + mv0.x, st0.x * v0);
    red_add_f32(dxdt + mv0.y, st0.y * v1);
    red_add_f32(dxdt + mv0.z, st0.z * v2);
    red_add_f32(dxdt + mv0.w, st0.w * v3);
    red_add_f32(dxdt + mv1.x, st1.x * v4);
    red_add_f32(dxdt + mv1.y, st1.y * v5);
    red_add_f32(dxdt + mv1.z, st1.z * v6);
    red_add_f32(dxdt + mv1.w, st1.w * v7);
}

// ---------------------------------------------------------------------------
// Launch
// ---------------------------------------------------------------------------
extern "C" void kernel_launch(void* const* d_in, const int* in_sizes, int n_in,
                              void* d_out, int out_size) {
    const float* x_met   = (const float*)d_in[0];
    const float* sto_sub = (const float*)d_in[1];
    const float* sto_all = (const float*)d_in[2];
    const float* W1m     = (const float*)d_in[3];
    const float* b1m     = (const float*)d_in[4];
    const float* W2m     = (const float*)d_in[5];
    const float* b2m     = (const float*)d_in[6];
    const float* W1r     = (const float*)d_in[7];
    const float* b1r     = (const float*)d_in[8];
    const float* W2r     = (const float*)d_in[9];
    const float* b2r     = (const float*)d_in[10];
    const int*   met_sub = (const int*)d_in[11];
    const int*   rxn_sub = (const int*)d_in[12];
    const int*   met_all = (const int*)d_in[13];
    const int*   rxn_all = (const int*)d_in[14];

    float* dxdt = (float*)d_out;
    float* v    = (float*)d_out + N_MET;

    // zero via async memset (graph-capturable, no kernel launch)
    void* hrxn_ptr = nullptr;
    cudaGetSymbolAddress(&hrxn_ptr, g_hrxn);
    cudaMemsetAsync(hrxn_ptr, 0, N_RXN * MSG_DIM * sizeof(float));
    cudaMemsetAsync(dxdt, 0, N_MET * sizeof(float));

    int grid1 = (E_SUB + K1_EPB - 1) / K1_EPB;
    edge_msg_kernel<<<grid1, K1_TPB>>>(x_met, sto_sub, W1m, b1m, W2m, b2m,
                                       met_sub, rxn_sub);

    rate_kernel<<<(N_RXN + 255) / 256, 256>>>(W1r, b1r, W2r, b2r, v);

    dxdt_kernel<<<(E_ALL / K3_EPT + 255) / 256, 256>>>(sto_all, rxn_all, met_all, v, dxdt);
}

// round 6
// speedup vs baseline: 1.1253x; 1.1253x over previous
#include <cuda_runtime.h>
#include <cuda_bf16.h>
#include <cstdint>

// Problem constants
#define N_MET   100000
#define N_RXN   50000
#define E_SUB   2000000
#define E_ALL   4000000
#define MSG_DIM 16
#define HIDDEN  32

// Persistent scratch: per-reaction accumulated messages [N_RXN][16]
__device__ float g_hrxn[N_RXN * MSG_DIM];

// Edge-MLP weights in constant memory (filled by async D2D copies each launch).
// cW2p: W2m [32][16] row-major reinterpreted as 8 packed f32-pairs per row.
__constant__ unsigned long long cW2p[HIDDEN * (MSG_DIM / 2)];
__constant__ float cW1[2 * HIDDEN];   // row 0: x-weights, row 1: s-weights
__constant__ float cB1[HIDDEN];
__constant__ float cB2[MSG_DIM];

// ---------------------------------------------------------------------------
// helpers
// ---------------------------------------------------------------------------
__device__ __forceinline__ unsigned long long pack2(float a, float b) {
    unsigned long long r;
    asm("mov.b64 %0, {%1,%2};" : "=l"(r) : "f"(a), "f"(b));
    return r;
}
__device__ __forceinline__ unsigned long long fma2(unsigned long long a,
                                                   unsigned long long b,
                                                   unsigned long long c) {
    unsigned long long d;
    asm("fma.rn.f32x2 %0, %1, %2, %3;" : "=l"(d) : "l"(a), "l"(b), "l"(c));
    return d;
}
__device__ __forceinline__ float2 unpack2(unsigned long long a) {
    float2 f;
    asm("mov.b64 {%0,%1}, %2;" : "=f"(f.x), "=f"(f.y) : "l"(a));
    return f;
}
__device__ __forceinline__ float fast_ex2(float x) {
    float y; asm("ex2.approx.ftz.f32 %0, %1;" : "=f"(y) : "f"(x)); return y;
}
__device__ __forceinline__ float fast_rcp(float x) {
    float y; asm("rcp.approx.ftz.f32 %0, %1;" : "=f"(y) : "f"(x)); return y;
}
// single-MUFU tanh (MUFU.TANH) — edge kernel (measured: no precision impact)
__device__ __forceinline__ float tanh_fast(float x) {
    float y; asm("tanh.approx.f32 %0, %1;" : "=f"(y) : "f"(x)); return y;
}
// accurate tanh via ex2+rcp (input pre-scaled by 2*log2(e)) — rate kernel
__device__ __forceinline__ float tanh_from_scaled(float u_scaled) {
    float e = fast_ex2(u_scaled);
    float r = fast_rcp(e + 1.0f);
    return fmaf(-2.0f, r, 1.0f);
}

__device__ __forceinline__ void red_add_v4(float* p, float a, float b, float c, float d) {
    asm volatile("red.global.add.v4.f32 [%0], {%1,%2,%3,%4};"
                 :: "l"(p), "f"(a), "f"(b), "f"(c), "f"(d) : "memory");
}
__device__ __forceinline__ void red_add_f32(float* p, float a) {
    asm volatile("red.global.add.f32 [%0], %1;" :: "l"(p), "f"(a) : "memory");
}

// ---------------------------------------------------------------------------
// Kernel 1: per-edge message MLP + scatter-add into g_hrxn
//   msg = tanh([x,s] @ W1m + b1m) @ W2m + b2m      (2->32->16)
// Each thread owns 4 CONTIGUOUS edges -> vectorized int4/float4 stream loads.
// Weights come from __constant__ (constant port, not L1tex).
// ---------------------------------------------------------------------------
#define K1_TPB 128
#define K1_EPT 4
#define K1_EPB (K1_TPB * K1_EPT)

__global__ __launch_bounds__(K1_TPB)
void edge_msg_kernel(const float* __restrict__ x_met,
                     const float* __restrict__ sto_sub,
                     const int*   __restrict__ met_sub,
                     const int*   __restrict__ rxn_sub) {
    const int tid4 = blockIdx.x * K1_TPB + threadIdx.x;   // quad index
    const int e0 = tid4 * K1_EPT;
    if (e0 >= E_SUB) return;                              // E_SUB % 4 == 0

    // 3 vector stream loads (LDG.128) + 4 gathers
    int4   mi = __ldcs(reinterpret_cast<const int4*>(met_sub) + tid4);
    float4 sv = __ldcs(reinterpret_cast<const float4*>(sto_sub) + tid4);
    int4   ri = __ldcs(reinterpret_cast<const int4*>(rxn_sub) + tid4);

    float x[K1_EPT], s[K1_EPT];
    x[0] = __ldg(x_met + mi.x); x[1] = __ldg(x_met + mi.y);
    x[2] = __ldg(x_met + mi.z); x[3] = __ldg(x_met + mi.w);
    s[0] = sv.x; s[1] = sv.y; s[2] = sv.z; s[3] = sv.w;

    // accumulators init = b2m
    unsigned long long acc[K1_EPT][MSG_DIM / 2];
    #pragma unroll
    for (int q = 0; q < MSG_DIM / 2; q++) {
        unsigned long long b = pack2(cB2[2 * q], cB2[2 * q + 1]);
        #pragma unroll
        for (int k = 0; k < K1_EPT; k++) acc[k][q] = b;
    }

    #pragma unroll 2
    for (int j = 0; j < HIDDEN; j++) {
        const float wa = cW1[j], wb = cW1[HIDDEN + j], bj = cB1[j];
        float h[K1_EPT];
        #pragma unroll
        for (int k = 0; k < K1_EPT; k++) {
            float u = fmaf(x[k], wa, fmaf(s[k], wb, bj));
            h[k] = tanh_fast(u);
        }
        #pragma unroll
        for (int k = 0; k < K1_EPT; k++) {
            unsigned long long hh = pack2(h[k], h[k]);
            #pragma unroll
            for (int q = 0; q < MSG_DIM / 2; q++)
                acc[k][q] = fma2(hh, cW2p[j * (MSG_DIM / 2) + q], acc[k][q]);
        }
    }

    const int rx[K1_EPT] = {ri.x, ri.y, ri.z, ri.w};
    #pragma unroll
    for (int k = 0; k < K1_EPT; k++) {
        float* p = g_hrxn + (size_t)rx[k] * MSG_DIM;
        #pragma unroll
        for (int q = 0; q < 4; q++) {
            float2 a = unpack2(acc[k][2 * q]);
            float2 b = unpack2(acc[k][2 * q + 1]);
            red_add_v4(p + 4 * q, a.x, a.y, b.x, b.y);
        }
    }
}

// ---------------------------------------------------------------------------
// Kernel 2: per-reaction rate MLP (exact tanh for precision headroom)
// ---------------------------------------------------------------------------
__global__ __launch_bounds__(256)
void rate_kernel(const float* __restrict__ W1r,
                 const float* __restrict__ b1r,
                 const float* __restrict__ W2r,
                 const float* __restrict__ b2r,
                 float* __restrict__ v_out) {
    __shared__ float sW1r[MSG_DIM * HIDDEN];
    __shared__ float sb1r[HIDDEN];
    __shared__ float sW2r[HIDDEN];
    __shared__ float sb2r;

    int t = threadIdx.x;
    for (int i = t; i < MSG_DIM * HIDDEN; i += blockDim.x) sW1r[i] = W1r[i];
    if (t < HIDDEN) { sb1r[t] = b1r[t]; sW2r[t] = W2r[t]; }
    if (t == 0) sb2r = b2r[0];
    __syncthreads();

    int r = blockIdx.x * blockDim.x + t;
    if (r >= N_RXN) return;

    float h[MSG_DIM];
    const float4* hp = reinterpret_cast<const float4*>(g_hrxn + (size_t)r * MSG_DIM);
    #pragma unroll
    for (int q = 0; q < 4; q++) {
        float4 hv = hp[q];
        h[4 * q] = hv.x; h[4 * q + 1] = hv.y; h[4 * q + 2] = hv.z; h[4 * q + 3] = hv.w;
    }

    const float C = 2.8853900817779268f;  // 2*log2(e)
    float y = sb2r;
    #pragma unroll 8
    for (int j = 0; j < HIDDEN; j++) {
        float a = sb1r[j];
        #pragma unroll
        for (int k = 0; k < MSG_DIM; k++) a = fmaf(h[k], sW1r[k * HIDDEN + j], a);
        float z = tanh_from_scaled(a * C);
        y = fmaf(z, sW2r[j], y);
    }
    float sp = fmaxf(y, 0.f) + log1pf(expf(-fabsf(y)));
    v_out[r] = sp;
}

// ---------------------------------------------------------------------------
// Kernel 3: dxdt scatter — exact R1 winner shape (33.0 us measured)
// ---------------------------------------------------------------------------
__global__ __launch_bounds__(256)
void dxdt_kernel(const float* __restrict__ sto_all,
                 const int*   __restrict__ rxn_all,
                 const int*   __restrict__ met_all,
                 const float* __restrict__ v,
                 float* __restrict__ dxdt) {
    int i4 = blockIdx.x * blockDim.x + threadIdx.x;   // one thread = 4 edges
    if (i4 >= E_ALL / 4) return;
    float4 sv = reinterpret_cast<const float4*>(sto_all)[i4];
    int4   rv = reinterpret_cast<const int4*>(rxn_all)[i4];
    int4   mv = reinterpret_cast<const int4*>(met_all)[i4];
    red_add_f32(dxdt + mv.x, sv.x * __ldg(v + rv.x));
    red_add_f32(dxdt + mv.y, sv.y * __ldg(v + rv.y));
    red_add_f32(dxdt + mv.z, sv.z * __ldg(v + rv.z));
    red_add_f32(dxdt + mv.w, sv.w * __ldg(v + rv.w));
}

// ---------------------------------------------------------------------------
// Launch
// ---------------------------------------------------------------------------
extern "C" void kernel_launch(void* const* d_in, const int* in_sizes, int n_in,
                              void* d_out, int out_size) {
    const float* x_met   = (const float*)d_in[0];
    const float* sto_sub = (const float*)d_in[1];
    const float* sto_all = (const float*)d_in[2];
    const float* W1m     = (const float*)d_in[3];
    const float* b1m     = (const float*)d_in[4];
    const float* W2m     = (const float*)d_in[5];
    const float* b2m     = (const float*)d_in[6];
    const float* W1r     = (const float*)d_in[7];
    const float* b1r     = (const float*)d_in[8];
    const float* W2r     = (const float*)d_in[9];
    const float* b2r     = (const float*)d_in[10];
    const int*   met_sub = (const int*)d_in[11];
    const int*   rxn_sub = (const int*)d_in[12];
    const int*   met_all = (const int*)d_in[13];
    const int*   rxn_all = (const int*)d_in[14];

    float* dxdt = (float*)d_out;
    float* v    = (float*)d_out + N_MET;

    // fill constant-memory weights (device-to-device async copies: capturable)
    cudaMemcpyToSymbolAsync(cW2p, W2m, HIDDEN * MSG_DIM * sizeof(float), 0,
                            cudaMemcpyDeviceToDevice);
    cudaMemcpyToSymbolAsync(cW1,  W1m, 2 * HIDDEN * sizeof(float), 0,
                            cudaMemcpyDeviceToDevice);
    cudaMemcpyToSymbolAsync(cB1,  b1m, HIDDEN * sizeof(float), 0,
                            cudaMemcpyDeviceToDevice);
    cudaMemcpyToSymbolAsync(cB2,  b2m, MSG_DIM * sizeof(float), 0,
                            cudaMemcpyDeviceToDevice);

    // zero scratch + dxdt
    void* hrxn_ptr = nullptr;
    cudaGetSymbolAddress(&hrxn_ptr, g_hrxn);
    cudaMemsetAsync(hrxn_ptr, 0, N_RXN * MSG_DIM * sizeof(float));
    cudaMemsetAsync(dxdt, 0, N_MET * sizeof(float));

    int grid1 = (E_SUB / K1_EPT + K1_TPB - 1) / K1_TPB;
    edge_msg_kernel<<<grid1, K1_TPB>>>(x_met, sto_sub, met_sub, rxn_sub);

    rate_kernel<<<(N_RXN + 255) / 256, 256>>>(W1r, b1r, W2r, b2r, v);

    dxdt_kernel<<<(E_ALL / 4 + 255) / 256, 256>>>(sto_all, rxn_all, met_all, v, dxdt);
}